// round 16
// baseline (speedup 1.0000x reference)
#include <cuda_runtime.h>
#include <cuda.h>
#include <cuda_fp16.h>
#include <math.h>

#define EMBED 512
#define HEADS 8
#define DEPTH 64
#define BATCH 2
#define SEQ   4096
#define MROWS (BATCH * SEQ)          // 8192

typedef unsigned long long u64;
typedef unsigned int u32;

// ---------------------------------------------------------------------------
// Device scratch
// ---------------------------------------------------------------------------
__device__ uint4 g_Qc[16 * 32 * 8 * 4 * 32];          // Q A-frag cells (8 MB)
__device__ uint4 g_Ac[64 * 16 * 8 * 2 * 32];          // ctx A-frag cells (8 MB)
__device__ uint4 g_Wc[4 * 64 * 32 * 32];              // packed W B-cells (hi+lo)
__device__ uint4 g_Kc[BATCH * HEADS * 64 * 512];      // K cells, 64-key tiles
__device__ uint4 g_Vc[BATCH * HEADS * 64 * 512];      // V cells, 64-key tiles

// ---------------------------------------------------------------------------
// fp16 mma.sync + cp.async helpers (baseline PTX, compute_103-safe)
// ---------------------------------------------------------------------------
__device__ __forceinline__ void mma16(float c[4], const u32 a[4], u32 b0, u32 b1) {
    asm("mma.sync.aligned.m16n8k16.row.col.f32.f16.f16.f32 "
        "{%0,%1,%2,%3}, {%4,%5,%6,%7}, {%8,%9}, {%0,%1,%2,%3};"
        : "+f"(c[0]), "+f"(c[1]), "+f"(c[2]), "+f"(c[3])
        : "r"(a[0]), "r"(a[1]), "r"(a[2]), "r"(a[3]), "r"(b0), "r"(b1));
}
__device__ __forceinline__ u32 f2h2(float lo, float hi) {
    __half2 h = __float22half2_rn(make_float2(lo, hi));
    return *(u32*)&h;
}
__device__ __forceinline__ float2 h22f(u32 v) {
    __half2 h = *(__half2*)&v;
    return __half22float2(h);
}
__device__ __forceinline__ void split2(float2 x, u32& hi, u32& lo) {
    hi = f2h2(x.x, x.y);
    float2 back = h22f(hi);
    lo = f2h2(x.x - back.x, x.y - back.y);
}
__device__ __forceinline__ u32 packhh(__half a, __half b) {
    return (u32)__half_as_ushort(a) | ((u32)__half_as_ushort(b) << 16);
}
__device__ __forceinline__ u32 smem_u32(const void* p) {
    u32 a;
    asm("{ .reg .u64 t; cvta.to.shared.u64 t, %1; cvt.u32.u64 %0, t; }"
        : "=r"(a) : "l"(p));
    return a;
}
__device__ __forceinline__ void cpa16(u32 saddr, const void* gptr) {
    asm volatile("cp.async.cg.shared.global [%0], [%1], 16;"
                 :: "r"(saddr), "l"(gptr));
}
__device__ __forceinline__ float ex2f(float x) {
    float r; asm("ex2.approx.f32 %0, %1;" : "=f"(r) : "f"(x)); return r;
}
#define CP_COMMIT() asm volatile("cp.async.commit_group;" ::: "memory")
#define CP_WAIT(n)  asm volatile("cp.async.wait_group %0;" :: "n"(n) : "memory")

#define SCL_L2E  0.180336890f        // 0.125 * log2(e)
#define MSK_L2E  (-1.442695041e9f)   // -1e9 * log2(e)

// ---------------------------------------------------------------------------
// Weight prep x4: W[512][512] -> cells [ntg 64][ksg 32][ln 32] (hi+lo)
// ---------------------------------------------------------------------------
__global__ __launch_bounds__(256) void wprep4_kernel(
    const float* __restrict__ W0, const float* __restrict__ W1,
    const float* __restrict__ W2, const float* __restrict__ W3,
    uint4* __restrict__ out)
{
    __shared__ float sw[32][132];
    const int tid = threadIdx.x;
    const int n0 = blockIdx.x * 128;
    const int k0 = blockIdx.y * 32;
    const int wz = blockIdx.z;
    const float* W = (wz == 0) ? W0 : (wz == 1) ? W1 : (wz == 2) ? W2 : W3;
    uint4* o = out + (size_t)wz * (64 * 32 * 32);

#pragma unroll
    for (int it = 0; it < 4; ++it) {
        int idx = tid + it * 256;
        int row = idx >> 5;
        int n4  = (idx & 31) * 4;
        *(float4*)&sw[row][n4] = *(const float4*)(W + (size_t)(k0 + row) * 512 + n0 + n4);
    }
    __syncthreads();

#pragma unroll
    for (int it = 0; it < 4; ++it) {
        int idx = tid + it * 256;
        int ln = idx & 31, ks = (idx >> 5) & 1, nt = idx >> 6;
        int gg = ln >> 2, tt = ln & 3;
        int nl = nt * 8 + gg;
        int kl = ks * 16 + 2 * tt;
        float2 x0 = make_float2(sw[kl][nl],     sw[kl + 1][nl]);
        float2 x1 = make_float2(sw[kl + 8][nl], sw[kl + 9][nl]);
        uint4 cv;
        split2(x0, cv.x, cv.z);
        split2(x1, cv.y, cv.w);
        o[((size_t)(blockIdx.x * 16 + nt) * 32 + blockIdx.y * 2 + ks) * 32 + ln] = cv;
    }
}

// ---------------------------------------------------------------------------
// QKV GEMM mainloop: fp32 A staging, 2-term hi/lo, 3-stage ring, one sync.
// ---------------------------------------------------------------------------
#define ASTR 36
#define SG_BOFF 55296
#define SG_TOT  104448
#define HST 132

__device__ __forceinline__ void gemm_issue_chunk(
    const float* __restrict__ A, const uint4* __restrict__ Wc,
    u32 sb, int m0, int nblk, int tid, int st, int kn)
{
#pragma unroll
    for (int it = 0; it < 4; ++it) {
        int idx = tid + it * 256;
        int row = idx >> 3, k4 = (idx & 7) * 4;
        cpa16(sb + st * 18432 + (row * ASTR + k4) * 4,
              A + (size_t)(m0 + row) * 512 + kn * 32 + k4);
        int ln = idx & 31, ks = (idx >> 5) & 1, nt = idx >> 6;
        cpa16(sb + SG_BOFF + st * 16384 + idx * 16,
              Wc + ((size_t)(nblk * 16 + nt) * 32 + kn * 2 + ks) * 32 + ln);
    }
    CP_COMMIT();
}

__device__ __forceinline__ void gemm_mainloop(
    const float* __restrict__ A, const uint4* __restrict__ Wc,
    const char* smem, u32 sb, int m0, int nblk,
    int tid, int w, int g, int t4, int lane, float acc[16][4])
{
#pragma unroll
    for (int nt = 0; nt < 16; ++nt)
#pragma unroll
        for (int e = 0; e < 4; ++e) acc[nt][e] = 0.0f;

    gemm_issue_chunk(A, Wc, sb, m0, nblk, tid, 0, 0);
    gemm_issue_chunk(A, Wc, sb, m0, nblk, tid, 1, 1);

    int cb = 0;
    for (int kc = 0; kc < 16; ++kc) {
        CP_WAIT(1);
        __syncthreads();

        int kn = (kc + 2 <= 15) ? kc + 2 : 15;
        int nb = (cb == 0) ? 2 : cb - 1;
        gemm_issue_chunk(A, Wc, sb, m0, nblk, tid, nb, kn);

        const float* arow = (const float*)(smem + cb * 18432) + (16 * w + g) * ASTR;
        const uint4* BCc  = (const uint4*)(smem + SG_BOFF + cb * 16384);

#pragma unroll
        for (int ks = 0; ks < 2; ++ks) {
            u32 ahi[4];
            const float* base = arow + ks * 16 + 2 * t4;
            float2 a0 = *(const float2*)(base);
            float2 a1 = *(const float2*)(base + 8 * ASTR);
            float2 a2 = *(const float2*)(base + 8);
            float2 a3 = *(const float2*)(base + 8 * ASTR + 8);
            ahi[0] = f2h2(a0.x, a0.y);
            ahi[1] = f2h2(a1.x, a1.y);
            ahi[2] = f2h2(a2.x, a2.y);
            ahi[3] = f2h2(a3.x, a3.y);
#pragma unroll
            for (int nt = 0; nt < 16; ++nt) {
                uint4 cv = BCc[(nt * 2 + ks) * 32 + lane];
                mma16(acc[nt], ahi, cv.x, cv.y);
                mma16(acc[nt], ahi, cv.z, cv.w);
            }
        }
        cb = (cb == 2) ? 0 : cb + 1;
    }
}

// ---------------------------------------------------------------------------
// Fused Q/K/V projection GEMM. grid (4 n, 64 m, 3 which).
// z=0: Q -> A-frag cells; z=1: K -> 64-tile B cells; z=2: V -> 64-tile B cells.
// ---------------------------------------------------------------------------
__global__ __launch_bounds__(256, 2) void gemm_qkv(
    const float* __restrict__ q, const float* __restrict__ k,
    const float* __restrict__ v, const uint4* __restrict__ Wc,
    const float* __restrict__ bq, const float* __restrict__ bk,
    const float* __restrict__ bv, u32* __restrict__ Qc,
    u32* __restrict__ Kc, u32* __restrict__ Vc)
{
    extern __shared__ char smem[];
    const u32 sb = smem_u32(smem);

    const int tid  = threadIdx.x;
    const int w    = tid >> 5;
    const int lane = tid & 31;
    const int g    = lane >> 2;
    const int t4   = lane & 3;
    const int n0   = blockIdx.x * 128;
    const int m0   = blockIdx.y * 128;
    const int z    = blockIdx.z;

    const float* A    = (z == 0) ? q : (z == 1) ? k : v;
    const float* bias = (z == 0) ? bq : (z == 1) ? bk : bv;
    const uint4* Wcz  = Wc + (size_t)z * (64 * 32 * 32);

    float acc[16][4];
    gemm_mainloop(A, Wcz, smem, sb, m0, blockIdx.x, tid, w, g, t4, lane, acc);

    const int m = m0 + 16 * w + g;
    if (z == 0) {
        int b = m >> 12, s = m & 4095;
        int qt = s >> 7;
#pragma unroll
        for (int nt = 0; nt < 16; ++nt) {
            int n = n0 + nt * 8 + 2 * t4;
            int h = n >> 6;
            float2 bi = *(const float2*)(bias + n);
            int ks = (nt & 7) >> 1;
            size_t cell4 = ((((size_t)(b * 8 + h) * 32 + qt) * 8 + w) * 4 + ks) * 32 + lane;
            Qc[cell4 * 4 + (nt & 1) * 2]     = f2h2(acc[nt][0] + bi.x, acc[nt][1] + bi.y);
            Qc[cell4 * 4 + (nt & 1) * 2 + 1] = f2h2(acc[nt][2] + bi.x, acc[nt][3] + bi.y);
        }
    } else if (z == 1) {
        // K cells, 64-key tiles: tile = (bh, s>>6), 2048 u32 per tile.
        int b = m >> 12, s = m & 4095;
        int jt = s >> 6;
#pragma unroll
        for (int nt = 0; nt < 16; ++nt) {
            int n = n0 + nt * 8 + 2 * t4;
            int h = n >> 6, d = n & 63;
            float2 bi = *(const float2*)(bias + n);
            size_t tilebase = ((size_t)(b * HEADS + h) * 64 + jt) * 2048;  // u32
            int ksA = d >> 4, wbit = (d >> 3) & 1;
            int sub = (ksA >> 1) * 128 + (ksA & 1) * 2 + wbit;
            int ln0 = (s & 7) * 4 + t4;
            int i0 = ((s >> 3) & 7) * 256 + sub + ln0 * 4;
            int i1 = (((s + 8) >> 3) & 7) * 256 + sub + ln0 * 4;
            Kc[tilebase + i0] = f2h2(acc[nt][0] + bi.x, acc[nt][1] + bi.y);
            Kc[tilebase + i1] = f2h2(acc[nt][2] + bi.x, acc[nt][3] + bi.y);
        }
    } else {
        // V cells via fp16 smem transpose; 64-key tiles (two per 128-row block).
        __syncthreads();
        __half* Hs = (__half*)smem;         // [128 s][HST]
        const int r0 = 16 * w + g;
#pragma unroll
        for (int nt = 0; nt < 16; ++nt) {
            int n = nt * 8 + 2 * t4;
            float2 bi = *(const float2*)(bias + n0 + n);
            *(u32*)&Hs[r0 * HST + n]       = f2h2(acc[nt][0] + bi.x, acc[nt][1] + bi.y);
            *(u32*)&Hs[(r0 + 8) * HST + n] = f2h2(acc[nt][2] + bi.x, acc[nt][3] + bi.y);
        }
        __syncthreads();

        int b = m0 >> 12, jt0 = (m0 & 4095) >> 6;
#pragma unroll
        for (int it = 0; it < 16; ++it) {
            int c  = tid + it * 256;
            int hh = c >> 11;
            int cl = c & 2047;
            int ln = cl & 31, ks = (cl >> 5) & 7, ntv = cl >> 8;
            int gg = ln >> 2, tt = ln & 3;
            int nl = hh * 64 + ntv * 8 + gg;
            int j  = ks * 16 + 2 * tt;
            u32 w0 = packhh(Hs[j * HST + nl],       Hs[(j + 1) * HST + nl]);
            u32 w1 = packhh(Hs[(j + 8) * HST + nl], Hs[(j + 9) * HST + nl]);
            int hgl = (n0 >> 6) + hh;
            int jtoff = ks >> 2, ks4 = ks & 3;
            size_t tilebase = ((size_t)(b * HEADS + hgl) * 64 + jt0 + jtoff) * 2048;
            int base4 = (ntv * 2 + (ks4 >> 1)) * 128 + ln * 4 + (ks4 & 1) * 2;
            Vc[tilebase + base4]     = w0;
            Vc[tilebase + base4 + 1] = w1;
        }
    }
}

// ---------------------------------------------------------------------------
// Output GEMM: A = prepacked fp16 A-frag cells, B = Wo cells. 3-stage ring.
// ---------------------------------------------------------------------------
#define SGO_BOFF 24576
#define SGO_TOT  73728

__device__ __forceinline__ void gout_issue_chunk(
    const uint4* __restrict__ Ac, const uint4* __restrict__ Wc,
    u32 sb, int mtile, int nblk, int tid, int st, int kn)
{
#pragma unroll
    for (int it = 0; it < 2; ++it) {
        int idx = tid + it * 256;
        cpa16(sb + st * 8192 + idx * 16,
              Ac + (size_t)(mtile * 16 + kn) * 512 + idx);
    }
#pragma unroll
    for (int it = 0; it < 4; ++it) {
        int idx = tid + it * 256;
        int ln = idx & 31, ks = (idx >> 5) & 1, nt = idx >> 6;
        cpa16(sb + SGO_BOFF + st * 16384 + idx * 16,
              Wc + ((size_t)(nblk * 16 + nt) * 32 + kn * 2 + ks) * 32 + ln);
    }
    CP_COMMIT();
}

__global__ __launch_bounds__(256, 2) void gemm_out(
    const uint4* __restrict__ Ac, const uint4* __restrict__ Wc,
    const float* __restrict__ bias, float* __restrict__ C)
{
    extern __shared__ char smem[];
    const u32 sb = smem_u32(smem);

    const int tid  = threadIdx.x;
    const int w    = tid >> 5;
    const int lane = tid & 31;
    const int g    = lane >> 2;
    const int t4   = lane & 3;
    const int n0   = blockIdx.x * 128;
    const int mtile = blockIdx.y;

    float acc[16][4];
#pragma unroll
    for (int nt = 0; nt < 16; ++nt)
#pragma unroll
        for (int e = 0; e < 4; ++e) acc[nt][e] = 0.0f;

    gout_issue_chunk(Ac, Wc, sb, mtile, blockIdx.x, tid, 0, 0);
    gout_issue_chunk(Ac, Wc, sb, mtile, blockIdx.x, tid, 1, 1);

    int cb = 0;
    for (int kc = 0; kc < 16; ++kc) {
        CP_WAIT(1);
        __syncthreads();

        int kn = (kc + 2 <= 15) ? kc + 2 : 15;
        int nb = (cb == 0) ? 2 : cb - 1;
        gout_issue_chunk(Ac, Wc, sb, mtile, blockIdx.x, tid, nb, kn);

        const uint4* Abuf = (const uint4*)(smem + cb * 8192);
        const uint4* BCc  = (const uint4*)(smem + SGO_BOFF + cb * 16384);

#pragma unroll
        for (int ks = 0; ks < 2; ++ks) {
            uint4 av = Abuf[(w * 2 + ks) * 32 + lane];
            u32 ahi[4] = { av.x, av.y, av.z, av.w };
#pragma unroll
            for (int nt = 0; nt < 16; ++nt) {
                uint4 cv = BCc[(nt * 2 + ks) * 32 + lane];
                mma16(acc[nt], ahi, cv.x, cv.y);
                mma16(acc[nt], ahi, cv.z, cv.w);
            }
        }
        cb = (cb == 2) ? 0 : cb + 1;
    }

    const int m = mtile * 128 + 16 * w + g;
#pragma unroll
    for (int nt = 0; nt < 16; ++nt) {
        int n = n0 + nt * 8 + 2 * t4;
        float2 bi = *(const float2*)(bias + n);
        *(float2*)(C + (size_t)m * 512 + n) =
            make_float2(acc[nt][0] + bi.x, acc[nt][1] + bi.y);
        *(float2*)(C + (size_t)(m + 8) * 512 + n) =
            make_float2(acc[nt][2] + bi.x, acc[nt][3] + bi.y);
    }
}

// ---------------------------------------------------------------------------
// Flash attention: 64-key tiles, Q cells staged in smem, 3-stage K/V ring,
// one sync per tile, 3 CTAs/SM target.
// smem: mask 2x64 @0 ; Q @1024 (16K) ; K stages @17408+i*8192 ; V @41984+i*8192
// ---------------------------------------------------------------------------
#define SM_MASK 0
#define SM_Q    1024
#define SM_KS   (SM_Q + 16384)
#define SM_VS   (SM_KS + 3 * 8192)
#define SM_TOT  (SM_VS + 3 * 8192)    // 66560

__global__ __launch_bounds__(256, 3) void attn_mma(
    const uint4* __restrict__ Qc, const uint4* __restrict__ Kc,
    const uint4* __restrict__ Vc, const float* __restrict__ mask,
    u32* __restrict__ Ac)
{
    extern __shared__ char smem[];
    const u32 sb = smem_u32(smem);
    float* smask = (float*)(smem + SM_MASK);   // [2][64]

    const int tid  = threadIdx.x;
    const int w    = tid >> 5;
    const int lane = tid & 31;
    const int t4   = lane & 3;
    const int bh   = blockIdx.y, b = bh >> 3, h = bh & 7;

    const uint4* Kcb = Kc + (size_t)bh * 64 * 512;
    const uint4* Vcb = Vc + (size_t)bh * 64 * 512;
    const float* mb  = mask + (size_t)b * SEQ;
    const uint4* QS  = (const uint4*)(smem + SM_Q);

    float oacc[8][4];
#pragma unroll
    for (int nt = 0; nt < 8; ++nt)
#pragma unroll
        for (int e = 0; e < 4; ++e) oacc[nt][e] = 0.0f;
    float ls0a = 0.0f, ls0b = 0.0f, ls1a = 0.0f, ls1b = 0.0f;

    // prologue: group A = Q cells + tile 0; group B = tile 1; mask(0)
    {
        const uint4* Qg = Qc + ((size_t)bh * 32 + blockIdx.x) * 1024;
#pragma unroll
        for (int it = 0; it < 4; ++it) {
            int c = tid + it * 256;
            cpa16(sb + SM_Q + c * 16, Qg + c);
        }
#pragma unroll
        for (int it = 0; it < 2; ++it) {
            int c = tid + it * 256;
            cpa16(sb + SM_KS + c * 16, Kcb + c);
            cpa16(sb + SM_VS + c * 16, Vcb + c);
        }
        CP_COMMIT();
#pragma unroll
        for (int it = 0; it < 2; ++it) {
            int c = tid + it * 256;
            cpa16(sb + SM_KS + 8192 + c * 16, Kcb + 512 + c);
            cpa16(sb + SM_VS + 8192 + c * 16, Vcb + 512 + c);
        }
        CP_COMMIT();
        if (tid < 64) smask[tid] = mb[tid] * MSK_L2E;
    }

    int cb = 0;
    for (int jt = 0; jt < 64; ++jt) {
        CP_WAIT(1);          // tile jt (and Q on jt=0) resident
        __syncthreads();     // compute(jt-1) done; mask(jt) visible

        int jn = (jt + 2 <= 63) ? jt + 2 : 63;
        int nb = (cb == 0) ? 2 : cb - 1;
        const uint4* ksrc = Kcb + (size_t)jn * 512;
        const uint4* vsrc = Vcb + (size_t)jn * 512;
#pragma unroll
        for (int it = 0; it < 2; ++it) {
            int c = tid + it * 256;
            cpa16(sb + SM_KS + nb * 8192 + c * 16, ksrc + c);
            cpa16(sb + SM_VS + nb * 8192 + c * 16, vsrc + c);
        }
        CP_COMMIT();

        if (tid < 64 && jt + 1 < 64)
            smask[((jt + 1) & 1) * 64 + tid] = mb[(jt + 1) * 64 + tid] * MSK_L2E;

        const uint4* KCb = (const uint4*)(smem + SM_KS + cb * 8192);
        const uint4* VCb = (const uint4*)(smem + SM_VS + cb * 8192);
        const float* mrow = smask + (jt & 1) * 64;

        // Q fragments from smem (per warp)
        u32 qh[4][4];
#pragma unroll
        for (int ks = 0; ks < 4; ++ks) {
            uint4 qv = QS[(w * 4 + ks) * 32 + lane];
            qh[ks][0] = qv.x; qh[ks][1] = qv.y;
            qh[ks][2] = qv.z; qh[ks][3] = qv.w;
        }

        // ---- QK^T + exp + pack ----
        u32 pa[4][4];
#pragma unroll
        for (int kp = 0; kp < 4; ++kp) {
            float sacc[2][4] = {{0.f,0.f,0.f,0.f},{0.f,0.f,0.f,0.f}};
#pragma unroll
            for (int i = 0; i < 2; ++i) {
                int nt = kp * 2 + i;
#pragma unroll
                for (int ksp = 0; ksp < 2; ++ksp) {
                    uint4 cv = KCb[(nt * 2 + ksp) * 32 + lane];
                    mma16(sacc[i], qh[2 * ksp],     cv.x, cv.y);
                    mma16(sacc[i], qh[2 * ksp + 1], cv.z, cv.w);
                }
            }
            float p[2][4];
#pragma unroll
            for (int i = 0; i < 2; ++i) {
                int c0 = (kp * 2 + i) * 8 + 2 * t4;
                float mk0 = mrow[c0], mk1 = mrow[c0 + 1];
                p[i][0] = ex2f(fmaf(sacc[i][0], SCL_L2E, mk0));
                p[i][1] = ex2f(fmaf(sacc[i][1], SCL_L2E, mk1));
                p[i][2] = ex2f(fmaf(sacc[i][2], SCL_L2E, mk0));
                p[i][3] = ex2f(fmaf(sacc[i][3], SCL_L2E, mk1));
            }
            if (kp & 1) {
                ls0b += (p[0][0] + p[0][1]) + (p[1][0] + p[1][1]);
                ls1b += (p[0][2] + p[0][3]) + (p[1][2] + p[1][3]);
            } else {
                ls0a += (p[0][0] + p[0][1]) + (p[1][0] + p[1][1]);
                ls1a += (p[0][2] + p[0][3]) + (p[1][2] + p[1][3]);
            }
            pa[kp][0] = f2h2(p[0][0], p[0][1]);
            pa[kp][1] = f2h2(p[0][2], p[0][3]);
            pa[kp][2] = f2h2(p[1][0], p[1][1]);
            pa[kp][3] = f2h2(p[1][2], p[1][3]);
        }

        // ---- O += P V ----
#pragma unroll
        for (int ksp = 0; ksp < 2; ++ksp) {
#pragma unroll
            for (int nt = 0; nt < 8; ++nt) {
                uint4 cv = VCb[(nt * 2 + ksp) * 32 + lane];
                mma16(oacc[nt], pa[2 * ksp],     cv.x, cv.y);
                mma16(oacc[nt], pa[2 * ksp + 1], cv.z, cv.w);
            }
        }
        cb = (cb == 2) ? 0 : cb + 1;
    }

    float lsum0 = ls0a + ls0b, lsum1 = ls1a + ls1b;
    lsum0 += __shfl_xor_sync(0xffffffffu, lsum0, 1);
    lsum0 += __shfl_xor_sync(0xffffffffu, lsum0, 2);
    lsum1 += __shfl_xor_sync(0xffffffffu, lsum1, 1);
    lsum1 += __shfl_xor_sync(0xffffffffu, lsum1, 2);
    float inv0 = 1.0f / lsum0, inv1 = 1.0f / lsum1;

    // epilogue: gemm_out A-frag cells
    const int mtile = b * 32 + blockIdx.x;
#pragma unroll
    for (int nt = 0; nt < 8; ++nt) {
        u32 w0 = f2h2(oacc[nt][0] * inv0, oacc[nt][1] * inv0);
        u32 w1 = f2h2(oacc[nt][2] * inv1, oacc[nt][3] * inv1);
        int kc = h * 2 + (nt >> 2);
        int ks = (nt >> 1) & 1;
        size_t cell4 = (((size_t)(mtile * 16 + kc) * 8 + w) * 2 + ks) * 32 + lane;
        Ac[cell4 * 4 + (nt & 1) * 2]     = w0;
        Ac[cell4 * 4 + (nt & 1) * 2 + 1] = w1;
    }
}

// ---------------------------------------------------------------------------
// Launcher
// ---------------------------------------------------------------------------
extern "C" void kernel_launch(void* const* d_in, const int* in_sizes, int n_in,
                              void* d_out, int out_size)
{
    const float* q    = (const float*)d_in[0];
    const float* k    = (const float*)d_in[1];
    const float* v    = (const float*)d_in[2];
    const float* mask = (const float*)d_in[3];
    const float* Wq   = (const float*)d_in[4];
    const float* bq   = (const float*)d_in[5];
    const float* Wk   = (const float*)d_in[6];
    const float* bk   = (const float*)d_in[7];
    const float* Wv   = (const float*)d_in[8];
    const float* bv   = (const float*)d_in[9];
    const float* Wo   = (const float*)d_in[10];
    const float* bo   = (const float*)d_in[11];
    float* out = (float*)d_out;

    uint4 *Qc, *Ac, *Wc, *Kc, *Vc;
    cudaGetSymbolAddress((void**)&Qc, g_Qc);
    cudaGetSymbolAddress((void**)&Ac, g_Ac);
    cudaGetSymbolAddress((void**)&Wc, g_Wc);
    cudaGetSymbolAddress((void**)&Kc, g_Kc);
    cudaGetSymbolAddress((void**)&Vc, g_Vc);

    const int WCN = 64 * 32 * 32;
    wprep4_kernel<<<dim3(4, 16, 4), 256>>>(Wq, Wk, Wv, Wo, Wc);

    cudaFuncSetAttribute(gemm_qkv, cudaFuncAttributeMaxDynamicSharedMemorySize, SG_TOT);
    cudaFuncSetAttribute(gemm_out, cudaFuncAttributeMaxDynamicSharedMemorySize, SGO_TOT);

    gemm_qkv<<<dim3(4, 64, 3), 256, SG_TOT>>>(
        q, k, v, Wc, bq, bk, bv, (u32*)Qc, (u32*)Kc, (u32*)Vc);

    cudaFuncSetAttribute(attn_mma, cudaFuncAttributeMaxDynamicSharedMemorySize, SM_TOT);
    attn_mma<<<dim3(SEQ / 128, BATCH * HEADS), 256, SM_TOT>>>(
        Qc, Kc, Vc, mask, (u32*)Ac);

    gemm_out<<<dim3(4, 64), 256, SGO_TOT>>>(Ac, Wc + 3 * WCN, bo, out);
}

// round 17
// speedup vs baseline: 1.0640x; 1.0640x over previous
#include <cuda_runtime.h>
#include <cuda.h>
#include <cuda_fp16.h>
#include <math.h>

#define EMBED 512
#define HEADS 8
#define DEPTH 64
#define BATCH 2
#define SEQ   4096
#define MROWS (BATCH * SEQ)          // 8192

typedef unsigned long long u64;
typedef unsigned int u32;

// ---------------------------------------------------------------------------
// Device scratch
// ---------------------------------------------------------------------------
__device__ uint4 g_Qc[16 * 32 * 8 * 4 * 32];          // Q A-frag cells (8 MB)
__device__ uint4 g_Ac[64 * 16 * 8 * 2 * 32];          // ctx A-frag cells (8 MB)
__device__ uint4 g_Wc[4 * 64 * 32 * 32];              // packed W B-cells (hi+lo)
__device__ uint4 g_Kc[BATCH * HEADS * 32 * 1024];     // K cells, 128-key tiles
__device__ uint4 g_Vc[BATCH * HEADS * 32 * 1024];     // V cells, 128-key tiles

// ---------------------------------------------------------------------------
// fp16 mma.sync + cp.async helpers (baseline PTX, compute_103-safe)
// ---------------------------------------------------------------------------
__device__ __forceinline__ void mma16(float c[4], const u32 a[4], u32 b0, u32 b1) {
    asm("mma.sync.aligned.m16n8k16.row.col.f32.f16.f16.f32 "
        "{%0,%1,%2,%3}, {%4,%5,%6,%7}, {%8,%9}, {%0,%1,%2,%3};"
        : "+f"(c[0]), "+f"(c[1]), "+f"(c[2]), "+f"(c[3])
        : "r"(a[0]), "r"(a[1]), "r"(a[2]), "r"(a[3]), "r"(b0), "r"(b1));
}
__device__ __forceinline__ u32 f2h2(float lo, float hi) {
    __half2 h = __float22half2_rn(make_float2(lo, hi));
    return *(u32*)&h;
}
__device__ __forceinline__ float2 h22f(u32 v) {
    __half2 h = *(__half2*)&v;
    return __half22float2(h);
}
__device__ __forceinline__ void split2(float2 x, u32& hi, u32& lo) {
    hi = f2h2(x.x, x.y);
    float2 back = h22f(hi);
    lo = f2h2(x.x - back.x, x.y - back.y);
}
__device__ __forceinline__ u32 packhh(__half a, __half b) {
    return (u32)__half_as_ushort(a) | ((u32)__half_as_ushort(b) << 16);
}
__device__ __forceinline__ u32 smem_u32(const void* p) {
    u32 a;
    asm("{ .reg .u64 t; cvta.to.shared.u64 t, %1; cvt.u32.u64 %0, t; }"
        : "=r"(a) : "l"(p));
    return a;
}
__device__ __forceinline__ void cpa16(u32 saddr, const void* gptr) {
    asm volatile("cp.async.cg.shared.global [%0], [%1], 16;"
                 :: "r"(saddr), "l"(gptr));
}
__device__ __forceinline__ float ex2f(float x) {
    float r; asm("ex2.approx.f32 %0, %1;" : "=f"(r) : "f"(x)); return r;
}
#define CP_COMMIT() asm volatile("cp.async.commit_group;" ::: "memory")
#define CP_WAIT(n)  asm volatile("cp.async.wait_group %0;" :: "n"(n) : "memory")

#define SCL_L2E  0.180336890f        // 0.125 * log2(e)
#define MSK_L2E  (-1.442695041e9f)   // -1e9 * log2(e)

// ---------------------------------------------------------------------------
// Weight prep x4: W[512][512] -> cells [ntg 64][ksg 32][ln 32] (hi+lo)
// ---------------------------------------------------------------------------
__global__ __launch_bounds__(256) void wprep4_kernel(
    const float* __restrict__ W0, const float* __restrict__ W1,
    const float* __restrict__ W2, const float* __restrict__ W3,
    uint4* __restrict__ out)
{
    __shared__ float sw[32][132];
    const int tid = threadIdx.x;
    const int n0 = blockIdx.x * 128;
    const int k0 = blockIdx.y * 32;
    const int wz = blockIdx.z;
    const float* W = (wz == 0) ? W0 : (wz == 1) ? W1 : (wz == 2) ? W2 : W3;
    uint4* o = out + (size_t)wz * (64 * 32 * 32);

#pragma unroll
    for (int it = 0; it < 4; ++it) {
        int idx = tid + it * 256;
        int row = idx >> 5;
        int n4  = (idx & 31) * 4;
        *(float4*)&sw[row][n4] = *(const float4*)(W + (size_t)(k0 + row) * 512 + n0 + n4);
    }
    __syncthreads();

#pragma unroll
    for (int it = 0; it < 4; ++it) {
        int idx = tid + it * 256;
        int ln = idx & 31, ks = (idx >> 5) & 1, nt = idx >> 6;
        int gg = ln >> 2, tt = ln & 3;
        int nl = nt * 8 + gg;
        int kl = ks * 16 + 2 * tt;
        float2 x0 = make_float2(sw[kl][nl],     sw[kl + 1][nl]);
        float2 x1 = make_float2(sw[kl + 8][nl], sw[kl + 9][nl]);
        uint4 cv;
        split2(x0, cv.x, cv.z);
        split2(x1, cv.y, cv.w);
        o[((size_t)(blockIdx.x * 16 + nt) * 32 + blockIdx.y * 2 + ks) * 32 + ln] = cv;
    }
}

// ---------------------------------------------------------------------------
// QKV GEMM mainloop: fp32 A staging, 2-term hi/lo, 3-stage ring, one sync.
// ---------------------------------------------------------------------------
#define ASTR 36
#define SG_BOFF 55296
#define SG_TOT  104448
#define HST 132

__device__ __forceinline__ void gemm_issue_chunk(
    const float* __restrict__ A, const uint4* __restrict__ Wc,
    u32 sb, int m0, int nblk, int tid, int st, int kn)
{
#pragma unroll
    for (int it = 0; it < 4; ++it) {
        int idx = tid + it * 256;
        int row = idx >> 3, k4 = (idx & 7) * 4;
        cpa16(sb + st * 18432 + (row * ASTR + k4) * 4,
              A + (size_t)(m0 + row) * 512 + kn * 32 + k4);
        int ln = idx & 31, ks = (idx >> 5) & 1, nt = idx >> 6;
        cpa16(sb + SG_BOFF + st * 16384 + idx * 16,
              Wc + ((size_t)(nblk * 16 + nt) * 32 + kn * 2 + ks) * 32 + ln);
    }
    CP_COMMIT();
}

__device__ __forceinline__ void gemm_mainloop(
    const float* __restrict__ A, const uint4* __restrict__ Wc,
    const char* smem, u32 sb, int m0, int nblk,
    int tid, int w, int g, int t4, int lane, float acc[16][4])
{
#pragma unroll
    for (int nt = 0; nt < 16; ++nt)
#pragma unroll
        for (int e = 0; e < 4; ++e) acc[nt][e] = 0.0f;

    gemm_issue_chunk(A, Wc, sb, m0, nblk, tid, 0, 0);
    gemm_issue_chunk(A, Wc, sb, m0, nblk, tid, 1, 1);

    int cb = 0;
    for (int kc = 0; kc < 16; ++kc) {
        CP_WAIT(1);
        __syncthreads();

        int kn = (kc + 2 <= 15) ? kc + 2 : 15;
        int nb = (cb == 0) ? 2 : cb - 1;
        gemm_issue_chunk(A, Wc, sb, m0, nblk, tid, nb, kn);

        const float* arow = (const float*)(smem + cb * 18432) + (16 * w + g) * ASTR;
        const uint4* BCc  = (const uint4*)(smem + SG_BOFF + cb * 16384);

#pragma unroll
        for (int ks = 0; ks < 2; ++ks) {
            u32 ahi[4];
            const float* base = arow + ks * 16 + 2 * t4;
            float2 a0 = *(const float2*)(base);
            float2 a1 = *(const float2*)(base + 8 * ASTR);
            float2 a2 = *(const float2*)(base + 8);
            float2 a3 = *(const float2*)(base + 8 * ASTR + 8);
            ahi[0] = f2h2(a0.x, a0.y);
            ahi[1] = f2h2(a1.x, a1.y);
            ahi[2] = f2h2(a2.x, a2.y);
            ahi[3] = f2h2(a3.x, a3.y);
#pragma unroll
            for (int nt = 0; nt < 16; ++nt) {
                uint4 cv = BCc[(nt * 2 + ks) * 32 + lane];
                mma16(acc[nt], ahi, cv.x, cv.y);
                mma16(acc[nt], ahi, cv.z, cv.w);
            }
        }
        cb = (cb == 2) ? 0 : cb + 1;
    }
}

// ---------------------------------------------------------------------------
// Fused Q/K/V projection GEMM. grid (4 n, 64 m, 3 which).  (R14 layouts)
// ---------------------------------------------------------------------------
__global__ __launch_bounds__(256, 2) void gemm_qkv(
    const float* __restrict__ q, const float* __restrict__ k,
    const float* __restrict__ v, const uint4* __restrict__ Wc,
    const float* __restrict__ bq, const float* __restrict__ bk,
    const float* __restrict__ bv, u32* __restrict__ Qc,
    u32* __restrict__ Kc, u32* __restrict__ Vc)
{
    extern __shared__ char smem[];
    const u32 sb = smem_u32(smem);

    const int tid  = threadIdx.x;
    const int w    = tid >> 5;
    const int lane = tid & 31;
    const int g    = lane >> 2;
    const int t4   = lane & 3;
    const int n0   = blockIdx.x * 128;
    const int m0   = blockIdx.y * 128;
    const int z    = blockIdx.z;

    const float* A    = (z == 0) ? q : (z == 1) ? k : v;
    const float* bias = (z == 0) ? bq : (z == 1) ? bk : bv;
    const uint4* Wcz  = Wc + (size_t)z * (64 * 32 * 32);

    float acc[16][4];
    gemm_mainloop(A, Wcz, smem, sb, m0, blockIdx.x, tid, w, g, t4, lane, acc);

    const int m = m0 + 16 * w + g;
    if (z == 0) {
        // Q A-frag cells: [bh][qtile128 32][warp 8][ks 4][lane 32] uint4
        int b = m >> 12, s = m & 4095;
        int qt = s >> 7;
#pragma unroll
        for (int nt = 0; nt < 16; ++nt) {
            int n = n0 + nt * 8 + 2 * t4;
            int h = n >> 6;
            float2 bi = *(const float2*)(bias + n);
            int ks = (nt & 7) >> 1;
            size_t cell4 = ((((size_t)(b * 8 + h) * 32 + qt) * 8 + w) * 4 + ks) * 32 + lane;
            Qc[cell4 * 4 + (nt & 1) * 2]     = f2h2(acc[nt][0] + bi.x, acc[nt][1] + bi.y);
            Qc[cell4 * 4 + (nt & 1) * 2 + 1] = f2h2(acc[nt][2] + bi.x, acc[nt][3] + bi.y);
        }
    } else if (z == 1) {
        int b = m >> 12, s = m & 4095;
        int jt = s >> 7;
#pragma unroll
        for (int nt = 0; nt < 16; ++nt) {
            int n = n0 + nt * 8 + 2 * t4;
            int h = n >> 6, d = n & 63;
            float2 bi = *(const float2*)(bias + n);
            size_t tilebase = ((size_t)(b * HEADS + h) * 32 + jt) * 4096;  // u32
            int ksA = d >> 4, wbit = (d >> 3) & 1;
            int sub = (ksA >> 1) * 128 + (ksA & 1) * 2 + wbit;
            int ln0 = (s & 7) * 4 + t4;
            int i0 = ((s >> 3) & 15) * 256 + sub + ln0 * 4;
            int i1 = (((s + 8) >> 3) & 15) * 256 + sub + ln0 * 4;
            Kc[tilebase + i0] = f2h2(acc[nt][0] + bi.x, acc[nt][1] + bi.y);
            Kc[tilebase + i1] = f2h2(acc[nt][2] + bi.x, acc[nt][3] + bi.y);
        }
    } else {
        // V cells via fp16 smem transpose (pairs along s), 128-key tiles.
        __syncthreads();
        __half* Hs = (__half*)smem;         // [128 s][HST]
        const int r0 = 16 * w + g;
#pragma unroll
        for (int nt = 0; nt < 16; ++nt) {
            int n = nt * 8 + 2 * t4;
            float2 bi = *(const float2*)(bias + n0 + n);
            *(u32*)&Hs[r0 * HST + n]       = f2h2(acc[nt][0] + bi.x, acc[nt][1] + bi.y);
            *(u32*)&Hs[(r0 + 8) * HST + n] = f2h2(acc[nt][2] + bi.x, acc[nt][3] + bi.y);
        }
        __syncthreads();

        int b = m0 >> 12, jt = (m0 & 4095) >> 7;
#pragma unroll
        for (int it = 0; it < 16; ++it) {
            int c  = tid + it * 256;
            int hh = c >> 11;
            int cl = c & 2047;
            int ln = cl & 31, ks = (cl >> 5) & 7, ntv = cl >> 8;
            int gg = ln >> 2, tt = ln & 3;
            int nl = hh * 64 + ntv * 8 + gg;
            int j  = ks * 16 + 2 * tt;
            u32 w0 = packhh(Hs[j * HST + nl],       Hs[(j + 1) * HST + nl]);
            u32 w1 = packhh(Hs[(j + 8) * HST + nl], Hs[(j + 9) * HST + nl]);
            int hgl = (n0 >> 6) + hh;
            size_t tilebase = ((size_t)(b * HEADS + hgl) * 32 + jt) * 4096;  // u32
            int base4 = (ntv * 4 + (ks >> 1)) * 128 + ln * 4 + (ks & 1) * 2;
            Vc[tilebase + base4]     = w0;
            Vc[tilebase + base4 + 1] = w1;
        }
    }
}

// ---------------------------------------------------------------------------
// Output GEMM: A = prepacked fp16 A-frag cells, B = Wo cells. 3-stage ring.
// ---------------------------------------------------------------------------
#define SGO_BOFF 24576
#define SGO_TOT  73728

__device__ __forceinline__ void gout_issue_chunk(
    const uint4* __restrict__ Ac, const uint4* __restrict__ Wc,
    u32 sb, int mtile, int nblk, int tid, int st, int kn)
{
#pragma unroll
    for (int it = 0; it < 2; ++it) {
        int idx = tid + it * 256;
        cpa16(sb + st * 8192 + idx * 16,
              Ac + (size_t)(mtile * 16 + kn) * 512 + idx);
    }
#pragma unroll
    for (int it = 0; it < 4; ++it) {
        int idx = tid + it * 256;
        int ln = idx & 31, ks = (idx >> 5) & 1, nt = idx >> 6;
        cpa16(sb + SGO_BOFF + st * 16384 + idx * 16,
              Wc + ((size_t)(nblk * 16 + nt) * 32 + kn * 2 + ks) * 32 + ln);
    }
    CP_COMMIT();
}

__global__ __launch_bounds__(256, 2) void gemm_out(
    const uint4* __restrict__ Ac, const uint4* __restrict__ Wc,
    const float* __restrict__ bias, float* __restrict__ C)
{
    extern __shared__ char smem[];
    const u32 sb = smem_u32(smem);

    const int tid  = threadIdx.x;
    const int w    = tid >> 5;
    const int lane = tid & 31;
    const int g    = lane >> 2;
    const int t4   = lane & 3;
    const int n0   = blockIdx.x * 128;
    const int mtile = blockIdx.y;

    float acc[16][4];
#pragma unroll
    for (int nt = 0; nt < 16; ++nt)
#pragma unroll
        for (int e = 0; e < 4; ++e) acc[nt][e] = 0.0f;

    gout_issue_chunk(Ac, Wc, sb, mtile, blockIdx.x, tid, 0, 0);
    gout_issue_chunk(Ac, Wc, sb, mtile, blockIdx.x, tid, 1, 1);

    int cb = 0;
    for (int kc = 0; kc < 16; ++kc) {
        CP_WAIT(1);
        __syncthreads();

        int kn = (kc + 2 <= 15) ? kc + 2 : 15;
        int nb = (cb == 0) ? 2 : cb - 1;
        gout_issue_chunk(Ac, Wc, sb, mtile, blockIdx.x, tid, nb, kn);

        const uint4* Abuf = (const uint4*)(smem + cb * 8192);
        const uint4* BCc  = (const uint4*)(smem + SGO_BOFF + cb * 16384);

#pragma unroll
        for (int ks = 0; ks < 2; ++ks) {
            uint4 av = Abuf[(w * 2 + ks) * 32 + lane];
            u32 ahi[4] = { av.x, av.y, av.z, av.w };
#pragma unroll
            for (int nt = 0; nt < 16; ++nt) {
                uint4 cv = BCc[(nt * 2 + ks) * 32 + lane];
                mma16(acc[nt], ahi, cv.x, cv.y);
                mma16(acc[nt], ahi, cv.z, cv.w);
            }
        }
        cb = (cb == 2) ? 0 : cb + 1;
    }

    const int m = mtile * 128 + 16 * w + g;
#pragma unroll
    for (int nt = 0; nt < 16; ++nt) {
        int n = n0 + nt * 8 + 2 * t4;
        float2 bi = *(const float2*)(bias + n);
        *(float2*)(C + (size_t)m * 512 + n) =
            make_float2(acc[nt][0] + bi.x, acc[nt][1] + bi.y);
        *(float2*)(C + (size_t)(m + 8) * 512 + n) =
            make_float2(acc[nt][2] + bi.x, acc[nt][3] + bi.y);
    }
}

// ---------------------------------------------------------------------------
// Flash attention: 256 Q rows/CTA (512 threads, 16 warps), 128-key tiles,
// 3-stage K/V ring, distance-2 prefetch, one sync per jtile.
// K/V smem traffic per unit work HALVED vs 128-row CTAs.
// smem: mask 2x128 @0; K stages @1024 + i*16384; V stages @50176 + i*16384.
// ---------------------------------------------------------------------------
#define SM_MASK 0
#define SM_KS   1024
#define SM_VS   (SM_KS + 3 * 16384)
#define SM_TOT  (SM_VS + 3 * 16384)   // 99328

__global__ __launch_bounds__(512, 1) void attn_mma(
    const uint4* __restrict__ Qc, const uint4* __restrict__ Kc,
    const uint4* __restrict__ Vc, const float* __restrict__ mask,
    u32* __restrict__ Ac)
{
    extern __shared__ char smem[];
    const u32 sb = smem_u32(smem);
    float* smask = (float*)(smem + SM_MASK);   // [2][128]

    const int tid  = threadIdx.x;
    const int w    = tid >> 5;        // 0..15
    const int w8   = w & 7;
    const int lane = tid & 31;
    const int t4   = lane & 3;
    const int bh   = blockIdx.y, b = bh >> 3, h = bh & 7;
    const int qt128 = blockIdx.x * 2 + (w >> 3);   // 128-row tile this warp maps to

    const uint4* Kcb = Kc + (size_t)bh * 32 * 1024;
    const uint4* Vcb = Vc + (size_t)bh * 32 * 1024;
    const float* mb  = mask + (size_t)b * SEQ;

    // Q fragments from prepacked cells: 4 x LDG.128 per warp
    u32 qhi[4][4];
    {
        const uint4* Qcb = Qc + (((size_t)bh * 32 + qt128) * 8 + w8) * 4 * 32;
#pragma unroll
        for (int ks = 0; ks < 4; ++ks) {
            uint4 qv = Qcb[ks * 32 + lane];
            qhi[ks][0] = qv.x; qhi[ks][1] = qv.y;
            qhi[ks][2] = qv.z; qhi[ks][3] = qv.w;
        }
    }

    float oacc[8][4];
#pragma unroll
    for (int nt = 0; nt < 8; ++nt)
#pragma unroll
        for (int e = 0; e < 4; ++e) oacc[nt][e] = 0.0f;
    float ls0a = 0.0f, ls0b = 0.0f, ls1a = 0.0f, ls1b = 0.0f;

    // prologue: stages 0 and 1, mask(0)   (1024 uint4 per K/V tile)
#pragma unroll
    for (int it = 0; it < 2; ++it) {
        int c = tid + it * 512;
        cpa16(sb + SM_KS + c * 16, Kcb + c);
        cpa16(sb + SM_VS + c * 16, Vcb + c);
    }
    CP_COMMIT();
#pragma unroll
    for (int it = 0; it < 2; ++it) {
        int c = tid + it * 512;
        cpa16(sb + SM_KS + 16384 + c * 16, Kcb + 1024 + c);
        cpa16(sb + SM_VS + 16384 + c * 16, Vcb + 1024 + c);
    }
    CP_COMMIT();
    if (tid < 128) smask[tid] = mb[tid] * MSK_L2E;

    int cb = 0;
    for (int jt = 0; jt < 32; ++jt) {
        CP_WAIT(1);          // tile jt resident
        __syncthreads();     // compute(jt-1) done; mask(jt) visible

        int jn = (jt + 2 <= 31) ? jt + 2 : 31;
        int nb = (cb == 0) ? 2 : cb - 1;
        const uint4* ksrc = Kcb + (size_t)jn * 1024;
        const uint4* vsrc = Vcb + (size_t)jn * 1024;
#pragma unroll
        for (int it = 0; it < 2; ++it) {
            int c = tid + it * 512;
            cpa16(sb + SM_KS + nb * 16384 + c * 16, ksrc + c);
            cpa16(sb + SM_VS + nb * 16384 + c * 16, vsrc + c);
        }
        CP_COMMIT();

        if (tid < 128 && jt + 1 < 32)
            smask[((jt + 1) & 1) * 128 + tid] = mb[(jt + 1) * 128 + tid] * MSK_L2E;

        const uint4* KCb = (const uint4*)(smem + SM_KS + cb * 16384);
        const uint4* VCb = (const uint4*)(smem + SM_VS + cb * 16384);
        const float* mrow = smask + (jt & 1) * 128;

        // ---- QK^T + exp + pack ----
        u32 pa[8][4];
#pragma unroll
        for (int kp = 0; kp < 8; ++kp) {
            float sacc[2][4] = {{0.f,0.f,0.f,0.f},{0.f,0.f,0.f,0.f}};
#pragma unroll
            for (int i = 0; i < 2; ++i) {
                int nt = kp * 2 + i;
#pragma unroll
                for (int ksp = 0; ksp < 2; ++ksp) {
                    uint4 cv = KCb[(nt * 2 + ksp) * 32 + lane];
                    mma16(sacc[i], qhi[2 * ksp],     cv.x, cv.y);
                    mma16(sacc[i], qhi[2 * ksp + 1], cv.z, cv.w);
                }
            }
            float p[2][4];
#pragma unroll
            for (int i = 0; i < 2; ++i) {
                int c0 = (kp * 2 + i) * 8 + 2 * t4;
                float mk0 = mrow[c0], mk1 = mrow[c0 + 1];
                p[i][0] = ex2f(fmaf(sacc[i][0], SCL_L2E, mk0));
                p[i][1] = ex2f(fmaf(sacc[i][1], SCL_L2E, mk1));
                p[i][2] = ex2f(fmaf(sacc[i][2], SCL_L2E, mk0));
                p[i][3] = ex2f(fmaf(sacc[i][3], SCL_L2E, mk1));
            }
            if (kp & 1) {
                ls0b += (p[0][0] + p[0][1]) + (p[1][0] + p[1][1]);
                ls1b += (p[0][2] + p[0][3]) + (p[1][2] + p[1][3]);
            } else {
                ls0a += (p[0][0] + p[0][1]) + (p[1][0] + p[1][1]);
                ls1a += (p[0][2] + p[0][3]) + (p[1][2] + p[1][3]);
            }
            pa[kp][0] = f2h2(p[0][0], p[0][1]);
            pa[kp][1] = f2h2(p[0][2], p[0][3]);
            pa[kp][2] = f2h2(p[1][0], p[1][1]);
            pa[kp][3] = f2h2(p[1][2], p[1][3]);
        }

        // ---- O += P V ----
#pragma unroll
        for (int ksp = 0; ksp < 4; ++ksp) {
#pragma unroll
            for (int nt = 0; nt < 8; ++nt) {
                uint4 cv = VCb[(nt * 4 + ksp) * 32 + lane];
                mma16(oacc[nt], pa[2 * ksp],     cv.x, cv.y);
                mma16(oacc[nt], pa[2 * ksp + 1], cv.z, cv.w);
            }
        }
        cb = (cb == 2) ? 0 : cb + 1;
    }

    float lsum0 = ls0a + ls0b, lsum1 = ls1a + ls1b;
    lsum0 += __shfl_xor_sync(0xffffffffu, lsum0, 1);
    lsum0 += __shfl_xor_sync(0xffffffffu, lsum0, 2);
    lsum1 += __shfl_xor_sync(0xffffffffu, lsum1, 1);
    lsum1 += __shfl_xor_sync(0xffffffffu, lsum1, 2);
    float inv0 = 1.0f / lsum0, inv1 = 1.0f / lsum1;

    // epilogue: gemm_out A-frag cells (same layout as R14)
    const int mtile = b * 32 + qt128;
#pragma unroll
    for (int nt = 0; nt < 8; ++nt) {
        u32 w0 = f2h2(oacc[nt][0] * inv0, oacc[nt][1] * inv0);
        u32 w1 = f2h2(oacc[nt][2] * inv1, oacc[nt][3] * inv1);
        int kc = h * 2 + (nt >> 2);
        int ks = (nt >> 1) & 1;
        size_t cell4 = (((size_t)(mtile * 16 + kc) * 8 + w8) * 2 + ks) * 32 + lane;
        Ac[cell4 * 4 + (nt & 1) * 2]     = w0;
        Ac[cell4 * 4 + (nt & 1) * 2 + 1] = w1;
    }
}

// ---------------------------------------------------------------------------
// Launcher
// ---------------------------------------------------------------------------
extern "C" void kernel_launch(void* const* d_in, const int* in_sizes, int n_in,
                              void* d_out, int out_size)
{
    const float* q    = (const float*)d_in[0];
    const float* k    = (const float*)d_in[1];
    const float* v    = (const float*)d_in[2];
    const float* mask = (const float*)d_in[3];
    const float* Wq   = (const float*)d_in[4];
    const float* bq   = (const float*)d_in[5];
    const float* Wk   = (const float*)d_in[6];
    const float* bk   = (const float*)d_in[7];
    const float* Wv   = (const float*)d_in[8];
    const float* bv   = (const float*)d_in[9];
    const float* Wo   = (const float*)d_in[10];
    const float* bo   = (const float*)d_in[11];
    float* out = (float*)d_out;

    uint4 *Qc, *Ac, *Wc, *Kc, *Vc;
    cudaGetSymbolAddress((void**)&Qc, g_Qc);
    cudaGetSymbolAddress((void**)&Ac, g_Ac);
    cudaGetSymbolAddress((void**)&Wc, g_Wc);
    cudaGetSymbolAddress((void**)&Kc, g_Kc);
    cudaGetSymbolAddress((void**)&Vc, g_Vc);

    const int WCN = 64 * 32 * 32;
    wprep4_kernel<<<dim3(4, 16, 4), 256>>>(Wq, Wk, Wv, Wo, Wc);

    cudaFuncSetAttribute(gemm_qkv, cudaFuncAttributeMaxDynamicSharedMemorySize, SG_TOT);
    cudaFuncSetAttribute(gemm_out, cudaFuncAttributeMaxDynamicSharedMemorySize, SGO_TOT);

    gemm_qkv<<<dim3(4, 64, 3), 256, SG_TOT>>>(
        q, k, v, Wc, bq, bk, bv, (u32*)Qc, (u32*)Kc, (u32*)Vc);

    cudaFuncSetAttribute(attn_mma, cudaFuncAttributeMaxDynamicSharedMemorySize, SM_TOT);
    attn_mma<<<dim3(SEQ / 256, BATCH * HEADS), 512, SM_TOT>>>(
        Qc, Kc, Vc, mask, (u32*)Ac);

    gemm_out<<<dim3(4, 64), 256, SGO_TOT>>>(Ac, Wc + 3 * WCN, bo, out);
}